// round 1
// baseline (speedup 1.0000x reference)
#include <cuda_runtime.h>

// Problem constants
#define NB 4
#define NS 1024
#define ND 1024
#define NF 4096
#define NV 32000
#define NL 4

// Scratch (device globals: no allocation allowed)
__device__ float g_x  [(size_t)NB * NS * ND];   // activation stream [B,S,D]
__device__ float g_tmp[(size_t)NB * NS * ND];   // attn_out / ffn_out [B,S,D]
__device__ float g_h  [(size_t)NB * NS * NF];   // ffn hidden [B,S,F]

// ---------------------------------------------------------------------------
// Embedding: x[b,s,:] = emb[tok]*sqrt(D) + pe[s,:]
// ---------------------------------------------------------------------------
__global__ void embed_kernel(const int* __restrict__ tokens,
                             const float* __restrict__ emb,
                             const float* __restrict__ pe,
                             float* __restrict__ x)
{
    int row = blockIdx.x;           // b*S + s
    int s = row & (NS - 1);
    int tok = tokens[row];
    const float scale = 32.0f;      // sqrt(1024)
    const float* e = emb + (long)tok * ND;
    const float* p = pe + (long)s * ND;
    float* xr = x + (long)row * ND;
    for (int d = threadIdx.x; d < ND; d += blockDim.x)
        xr[d] = e[d] * scale + p[d];
}

// ---------------------------------------------------------------------------
// SGEMM: C = alpha * A@B (+bias) (+relu). A[M,K] row-major.
// TRANSB=false: B[K,N] row-major.  TRANSB=true: B[N,K] row-major (C=A@B^T).
// 128x128 block tile, BK=8, 256 threads, 8x8 per-thread microtile.
// All dims are multiples of tile sizes (guaranteed by problem shapes).
// Batched via blockIdx.z with element strides sA/sB/sC.
// ---------------------------------------------------------------------------
template<bool TRANSB, bool RELU>
__global__ __launch_bounds__(256)
void sgemm_kernel(const float* __restrict__ A, const float* __restrict__ B,
                  float* __restrict__ C,
                  int M, int N, int K,
                  long sA, long sB, long sC,
                  float alpha, const float* __restrict__ bias)
{
    constexpr int BM = 128, BN = 128, BK = 8;
    __shared__ float As[BK][BM];
    __shared__ float Bs[BK][BN];

    A += (long)blockIdx.z * sA;
    B += (long)blockIdx.z * sB;
    C += (long)blockIdx.z * sC;

    const int brow = blockIdx.y * BM;
    const int bcol = blockIdx.x * BN;
    const int tid  = threadIdx.x;
    const int trow = tid >> 4;       // 0..15
    const int tcol = tid & 15;       // 0..15

    float acc[8][8] = {};

    // A tile load mapping: 128 rows x 8 cols = 256 float4 (along K)
    const int a_m = tid >> 1;
    const int a_k = (tid & 1) * 4;
    // B tile load mapping
    const int bt_n = tid >> 1;            // TRANSB: row of B (=n), float4 along K
    const int bt_k = (tid & 1) * 4;
    const int bn_k = tid >> 5;            // !TRANSB: row of B (=k)
    const int bn_n = (tid & 31) * 4;      // float4 along N

    for (int kk = 0; kk < K; kk += BK) {
        float4 av = *(const float4*)(A + (long)(brow + a_m) * K + kk + a_k);
        As[a_k + 0][a_m] = av.x;
        As[a_k + 1][a_m] = av.y;
        As[a_k + 2][a_m] = av.z;
        As[a_k + 3][a_m] = av.w;
        if (TRANSB) {
            float4 bv = *(const float4*)(B + (long)(bcol + bt_n) * K + kk + bt_k);
            Bs[bt_k + 0][bt_n] = bv.x;
            Bs[bt_k + 1][bt_n] = bv.y;
            Bs[bt_k + 2][bt_n] = bv.z;
            Bs[bt_k + 3][bt_n] = bv.w;
        } else {
            *(float4*)(&Bs[bn_k][bn_n]) =
                *(const float4*)(B + (long)(kk + bn_k) * N + bcol + bn_n);
        }
        __syncthreads();

        #pragma unroll
        for (int k = 0; k < BK; k++) {
            float rm[8], rn[8];
            *(float4*)(rm)     = *(const float4*)(&As[k][trow * 8]);
            *(float4*)(rm + 4) = *(const float4*)(&As[k][trow * 8 + 4]);
            *(float4*)(rn)     = *(const float4*)(&Bs[k][tcol * 8]);
            *(float4*)(rn + 4) = *(const float4*)(&Bs[k][tcol * 8 + 4]);
            #pragma unroll
            for (int i = 0; i < 8; i++)
                #pragma unroll
                for (int j = 0; j < 8; j++)
                    acc[i][j] = fmaf(rm[i], rn[j], acc[i][j]);
        }
        __syncthreads();
    }

    #pragma unroll
    for (int i = 0; i < 8; i++) {
        long crow = brow + trow * 8 + i;
        #pragma unroll
        for (int j = 0; j < 8; j += 4) {
            int c0 = bcol + tcol * 8 + j;
            float4 v;
            float b0 = bias ? bias[c0 + 0] : 0.0f;
            float b1 = bias ? bias[c0 + 1] : 0.0f;
            float b2 = bias ? bias[c0 + 2] : 0.0f;
            float b3 = bias ? bias[c0 + 3] : 0.0f;
            v.x = acc[i][j + 0] * alpha + b0;
            v.y = acc[i][j + 1] * alpha + b1;
            v.z = acc[i][j + 2] * alpha + b2;
            v.w = acc[i][j + 3] * alpha + b3;
            if (RELU) {
                v.x = fmaxf(v.x, 0.0f); v.y = fmaxf(v.y, 0.0f);
                v.z = fmaxf(v.z, 0.0f); v.w = fmaxf(v.w, 0.0f);
            }
            *(float4*)(C + crow * N + c0) = v;
        }
    }
}

// ---------------------------------------------------------------------------
// Causal softmax, in place on one [S] row of scores. Row id = b*S + s.
// Matches reference: masked (t>s) entries become exactly 0 after softmax.
// ---------------------------------------------------------------------------
__global__ __launch_bounds__(256)
void softmax_kernel(float* __restrict__ attn)
{
    int row = blockIdx.x;            // b*S + s
    int s = row & (NS - 1);
    float* p = attn + (long)row * NS;
    int tid = threadIdx.x;
    __shared__ float red[256];

    float vals[4];
    float mx = -1e30f;
    #pragma unroll
    for (int it = 0; it < 4; it++) {
        int j = tid + it * 256;
        float v = (j <= s) ? p[j] : -1e30f;
        vals[it] = v;
        mx = fmaxf(mx, v);
    }
    red[tid] = mx; __syncthreads();
    for (int o = 128; o > 0; o >>= 1) {
        if (tid < o) red[tid] = fmaxf(red[tid], red[tid + o]);
        __syncthreads();
    }
    mx = red[0]; __syncthreads();

    float sum = 0.0f;
    #pragma unroll
    for (int it = 0; it < 4; it++) {
        int j = tid + it * 256;
        float e = (j <= s) ? __expf(vals[it] - mx) : 0.0f;
        vals[it] = e;
        sum += e;
    }
    red[tid] = sum; __syncthreads();
    for (int o = 128; o > 0; o >>= 1) {
        if (tid < o) red[tid] += red[tid + o];
        __syncthreads();
    }
    float inv = 1.0f / red[0];
    #pragma unroll
    for (int it = 0; it < 4; it++) {
        int j = tid + it * 256;
        p[j] = vals[it] * inv;
    }
}

// ---------------------------------------------------------------------------
// LayerNorm over last dim D=1024 of (x + res): out = LN(x+res)*g + b.
// res may be null (final LN). In-place safe when out == x (per-row regs).
// ---------------------------------------------------------------------------
__global__ __launch_bounds__(256)
void ln_kernel(const float* __restrict__ x, const float* __restrict__ res,
               const float* __restrict__ g, const float* __restrict__ b,
               float* __restrict__ out)
{
    int row = blockIdx.x;
    const float* xr = x + (long)row * ND;
    const float* rr = res ? res + (long)row * ND : nullptr;
    float* o = out + (long)row * ND;
    int tid = threadIdx.x;
    __shared__ float red[256];

    float v[4];
    float lsum = 0.0f;
    #pragma unroll
    for (int it = 0; it < 4; it++) {
        int j = tid + it * 256;
        float t = xr[j] + (rr ? rr[j] : 0.0f);
        v[it] = t;
        lsum += t;
    }
    red[tid] = lsum; __syncthreads();
    for (int o2 = 128; o2 > 0; o2 >>= 1) {
        if (tid < o2) red[tid] += red[tid + o2];
        __syncthreads();
    }
    float mu = red[0] * (1.0f / ND); __syncthreads();

    float lvar = 0.0f;
    #pragma unroll
    for (int it = 0; it < 4; it++) {
        float d = v[it] - mu;
        lvar += d * d;
    }
    red[tid] = lvar; __syncthreads();
    for (int o2 = 128; o2 > 0; o2 >>= 1) {
        if (tid < o2) red[tid] += red[tid + o2];
        __syncthreads();
    }
    float rstd = rsqrtf(red[0] * (1.0f / ND) + 1e-5f);

    #pragma unroll
    for (int it = 0; it < 4; it++) {
        int j = tid + it * 256;
        o[j] = (v[it] - mu) * rstd * g[j] + b[j];
    }
}

// ---------------------------------------------------------------------------
// Launch
// ---------------------------------------------------------------------------
extern "C" void kernel_launch(void* const* d_in, const int* in_sizes, int n_in,
                              void* d_out, int out_size)
{
    const int*   tokens = (const int*)  d_in[0];
    // d_in[1] = mask (causal; handled analytically)
    const float* emb    = (const float*)d_in[2];
    const float* pe     = (const float*)d_in[3];
    const float* ln1_g  = (const float*)d_in[4];
    const float* ln1_b  = (const float*)d_in[5];
    const float* w1     = (const float*)d_in[6];
    const float* b1     = (const float*)d_in[7];
    const float* w2     = (const float*)d_in[8];
    const float* b2     = (const float*)d_in[9];
    const float* ln2_g  = (const float*)d_in[10];
    const float* ln2_b  = (const float*)d_in[11];
    const float* lnf_g  = (const float*)d_in[12];
    const float* lnf_b  = (const float*)d_in[13];
    const float* headW  = (const float*)d_in[14];
    const float* headb  = (const float*)d_in[15];

    float* out      = (float*)d_out;
    float* logits   = out;                               // [B,S,V]
    float* attn_all = out + (long)NB * NS * NV;          // [L,B,S,S]

    float *x, *tmp, *h;
    cudaGetSymbolAddress((void**)&x,   g_x);
    cudaGetSymbolAddress((void**)&tmp, g_tmp);
    cudaGetSymbolAddress((void**)&h,   g_h);

    const int ROWS = NB * NS;           // 4096
    const float inv_scale = 1.0f / 32.0f;

    embed_kernel<<<ROWS, 256>>>(tokens, emb, pe, x);

    for (int l = 0; l < NL; l++) {
        float* attnL = attn_all + (long)l * NB * NS * NS;

        // scores = x @ x^T / sqrt(D)   (per batch), written into d_out attn region
        sgemm_kernel<true, false><<<dim3(NS / 128, NS / 128, NB), 256>>>(
            x, x, attnL, NS, NS, ND,
            (long)NS * ND, (long)NS * ND, (long)NS * NS,
            inv_scale, nullptr);

        // causal softmax in place
        softmax_kernel<<<ROWS, 256>>>(attnL);

        // attn_out = attn @ x  (per batch)
        sgemm_kernel<false, false><<<dim3(ND / 128, NS / 128, NB), 256>>>(
            attnL, x, tmp, NS, ND, NS,
            (long)NS * NS, (long)NS * ND, (long)NS * ND,
            1.0f, nullptr);

        // x = LN(x + attn_out)
        ln_kernel<<<ROWS, 256>>>(x, tmp, ln1_g + l * ND, ln1_b + l * ND, x);

        // h = relu(x @ w1 + b1)
        sgemm_kernel<false, true><<<dim3(NF / 128, ROWS / 128, 1), 256>>>(
            x, w1 + (long)l * ND * NF, h, ROWS, NF, ND,
            0, 0, 0, 1.0f, b1 + (long)l * NF);

        // ffn_out = h @ w2 + b2
        sgemm_kernel<false, false><<<dim3(ND / 128, ROWS / 128, 1), 256>>>(
            h, w2 + (long)l * NF * ND, tmp, ROWS, ND, NF,
            0, 0, 0, 1.0f, b2 + (long)l * ND);

        // x = LN(x + ffn_out)
        ln_kernel<<<ROWS, 256>>>(x, tmp, ln2_g + l * ND, ln2_b + l * ND, x);
    }

    // final LN
    ln_kernel<<<ROWS, 256>>>(x, nullptr, lnf_g, lnf_b, x);

    // logits = x @ headW + headb
    sgemm_kernel<false, false><<<dim3(NV / 128, ROWS / 128, 1), 256>>>(
        x, headW, logits, ROWS, NV, ND,
        0, 0, 0, 1.0f, headb);
}

// round 2
// speedup vs baseline: 1.1747x; 1.1747x over previous
#include <cuda_runtime.h>
#include <cstring>

// Problem constants
#define NB 4
#define NS 1024
#define ND 1024
#define NF 4096
#define NV 32000
#define NL 4

// Scratch (device globals: no allocation allowed)
__device__ float g_x  [(size_t)NB * NS * ND];   // activation stream [B,S,D]
__device__ float g_tmp[(size_t)NB * NS * ND];   // attn_out / ffn_out [B,S,D]
__device__ float g_h  [(size_t)NB * NS * NF];   // ffn hidden [B,S,F]

// Packed fp32x2 FMA (exact fp32; ptxas never emits FFMA2 from C++)
#define FFMA2(d, a, b) \
    asm("fma.rn.f32x2 %0, %1, %2, %0;" : "+l"(d) : "l"(a), "l"(b))
#define PACK_DUP(out, x) \
    asm("mov.b64 %0, {%1, %1};" : "=l"(out) : "r"(__float_as_uint(x)))

// ---------------------------------------------------------------------------
// Embedding: x[b,s,:] = emb[tok]*sqrt(D) + pe[s,:]
// ---------------------------------------------------------------------------
__global__ void embed_kernel(const int* __restrict__ tokens,
                             const float* __restrict__ emb,
                             const float* __restrict__ pe,
                             float* __restrict__ x)
{
    int row = blockIdx.x;           // b*S + s
    int s = row & (NS - 1);
    int tok = tokens[row];
    const float scale = 32.0f;      // sqrt(1024)
    const float* e = emb + (long)tok * ND;
    const float* p = pe + (long)s * ND;
    float* xr = x + (long)row * ND;
    for (int d = threadIdx.x; d < ND; d += blockDim.x)
        xr[d] = e[d] * scale + p[d];
}

// ---------------------------------------------------------------------------
// SGEMM: C = alpha * A@B (+bias) (+relu). A[M,K] row-major.
// TRANSB=false: B[K,N] row-major.  TRANSB=true: B[N,K] row-major (C=A@B^T).
// CTRI: skip blocks strictly above the diagonal (causal scores, M==N).
// CKLIM: truncate K-loop at brow+BM (A has exact zeros beyond diagonal).
// 128x128 tile, BK=8, 256 threads, 8x8 microtile via packed f32x2 FMA,
// double-buffered shared memory.
// ---------------------------------------------------------------------------
template<bool TRANSB, bool RELU, bool CTRI, bool CKLIM>
__global__ __launch_bounds__(256)
void sgemm_kernel(const float* __restrict__ A, const float* __restrict__ B,
                  float* __restrict__ C,
                  int M, int N, int K,
                  long sA, long sB, long sC,
                  float alpha, const float* __restrict__ bias)
{
    constexpr int BM = 128, BN = 128, BK = 8;
    __shared__ float As[2][BK][BM];
    __shared__ float Bs[2][BK][BN];

    const int brow = blockIdx.y * BM;
    const int bcol = blockIdx.x * BN;
    if (CTRI && bcol > brow) return;          // fully masked block

    A += (long)blockIdx.z * sA;
    B += (long)blockIdx.z * sB;
    C += (long)blockIdx.z * sC;

    const int tid  = threadIdx.x;
    const int trow = tid >> 4;       // 0..15
    const int tcol = tid & 15;       // 0..15

    const int K_eff = CKLIM ? (brow + BM < K ? brow + BM : K) : K;

    // A tile load mapping: 128 rows x 8 cols = 256 float4 (along K)
    const int a_m = tid >> 1;
    const int a_k = (tid & 1) * 4;
    // B tile load mapping
    const int bt_n = tid >> 1;            // TRANSB: row of B (=n), float4 along K
    const int bt_k = (tid & 1) * 4;
    const int bn_k = tid >> 5;            // !TRANSB: row of B (=k)
    const int bn_n = (tid & 31) * 4;      // float4 along N

    const float* Aptr = A + (long)(brow + a_m) * K + a_k;
    const float* Bptr = TRANSB ? (B + (long)(bcol + bt_n) * K + bt_k)
                               : (B + (long)bn_k * N + bcol + bn_n);

    unsigned long long acc[8][4];
    {
        unsigned long long z; PACK_DUP(z, 0.0f);
        #pragma unroll
        for (int i = 0; i < 8; i++)
            #pragma unroll
            for (int j = 0; j < 4; j++) acc[i][j] = z;
    }

    // prologue: fill buffer 0
    {
        float4 av = *(const float4*)(Aptr);
        As[0][a_k + 0][a_m] = av.x;
        As[0][a_k + 1][a_m] = av.y;
        As[0][a_k + 2][a_m] = av.z;
        As[0][a_k + 3][a_m] = av.w;
        if (TRANSB) {
            float4 bv = *(const float4*)(Bptr);
            Bs[0][bt_k + 0][bt_n] = bv.x;
            Bs[0][bt_k + 1][bt_n] = bv.y;
            Bs[0][bt_k + 2][bt_n] = bv.z;
            Bs[0][bt_k + 3][bt_n] = bv.w;
        } else {
            *(float4*)(&Bs[0][bn_k][bn_n]) = *(const float4*)(Bptr);
        }
    }
    __syncthreads();

    int buf = 0;
    for (int kk = 0; kk < K_eff; kk += BK) {
        const bool has_next = (kk + BK) < K_eff;
        float4 av2, bv2;
        if (has_next) {
            av2 = *(const float4*)(Aptr + kk + BK);
            bv2 = TRANSB ? *(const float4*)(Bptr + kk + BK)
                         : *(const float4*)(Bptr + (long)(kk + BK) * N);
        }

        #pragma unroll
        for (int k = 0; k < BK; k++) {
            const float* as = &As[buf][k][trow * 8];
            float4 a0 = *(const float4*)(as);
            float4 a1 = *(const float4*)(as + 4);
            const ulonglong2* bs = (const ulonglong2*)(&Bs[buf][k][tcol * 8]);
            ulonglong2 b01 = bs[0];
            ulonglong2 b23 = bs[1];
            unsigned long long rb[4] = { b01.x, b01.y, b23.x, b23.y };
            float ra[8] = { a0.x, a0.y, a0.z, a0.w, a1.x, a1.y, a1.z, a1.w };
            #pragma unroll
            for (int i = 0; i < 8; i++) {
                unsigned long long am;
                PACK_DUP(am, ra[i]);
                #pragma unroll
                for (int j = 0; j < 4; j++)
                    FFMA2(acc[i][j], am, rb[j]);
            }
        }

        if (has_next) {
            int nb = buf ^ 1;
            As[nb][a_k + 0][a_m] = av2.x;
            As[nb][a_k + 1][a_m] = av2.y;
            As[nb][a_k + 2][a_m] = av2.z;
            As[nb][a_k + 3][a_m] = av2.w;
            if (TRANSB) {
                Bs[nb][bt_k + 0][bt_n] = bv2.x;
                Bs[nb][bt_k + 1][bt_n] = bv2.y;
                Bs[nb][bt_k + 2][bt_n] = bv2.z;
                Bs[nb][bt_k + 3][bt_n] = bv2.w;
            } else {
                *(float4*)(&Bs[nb][bn_k][bn_n]) = bv2;
            }
            __syncthreads();
            buf = nb;
        }
    }

    #pragma unroll
    for (int i = 0; i < 8; i++) {
        long crow = brow + trow * 8 + i;
        int c0 = bcol + tcol * 8;
        float vals[8];
        #pragma unroll
        for (int jp = 0; jp < 4; jp++) {
            float2 p;
            memcpy(&p, &acc[i][jp], 8);
            vals[2 * jp + 0] = p.x;
            vals[2 * jp + 1] = p.y;
        }
        #pragma unroll
        for (int j = 0; j < 8; j++) {
            float b = bias ? bias[c0 + j] : 0.0f;
            float v = vals[j] * alpha + b;
            if (RELU) v = fmaxf(v, 0.0f);
            vals[j] = v;
        }
        float4 v0 = { vals[0], vals[1], vals[2], vals[3] };
        float4 v1 = { vals[4], vals[5], vals[6], vals[7] };
        *(float4*)(C + crow * N + c0)     = v0;
        *(float4*)(C + crow * N + c0 + 4) = v1;
    }
}

// ---------------------------------------------------------------------------
// Causal softmax, in place on one [S] row of scores. Row id = b*S + s.
// Matches reference: masked (t>s) entries become exactly 0 after softmax.
// ---------------------------------------------------------------------------
__global__ __launch_bounds__(256)
void softmax_kernel(float* __restrict__ attn)
{
    int row = blockIdx.x;            // b*S + s
    int s = row & (NS - 1);
    float* p = attn + (long)row * NS;
    int tid = threadIdx.x;
    __shared__ float red[256];

    float vals[4];
    float mx = -1e30f;
    #pragma unroll
    for (int it = 0; it < 4; it++) {
        int j = tid + it * 256;
        float v = (j <= s) ? p[j] : -1e30f;
        vals[it] = v;
        mx = fmaxf(mx, v);
    }
    red[tid] = mx; __syncthreads();
    for (int o = 128; o > 0; o >>= 1) {
        if (tid < o) red[tid] = fmaxf(red[tid], red[tid + o]);
        __syncthreads();
    }
    mx = red[0]; __syncthreads();

    float sum = 0.0f;
    #pragma unroll
    for (int it = 0; it < 4; it++) {
        int j = tid + it * 256;
        float e = (j <= s) ? __expf(vals[it] - mx) : 0.0f;
        vals[it] = e;
        sum += e;
    }
    red[tid] = sum; __syncthreads();
    for (int o = 128; o > 0; o >>= 1) {
        if (tid < o) red[tid] += red[tid + o];
        __syncthreads();
    }
    float inv = 1.0f / red[0];
    #pragma unroll
    for (int it = 0; it < 4; it++) {
        int j = tid + it * 256;
        p[j] = vals[it] * inv;
    }
}

// ---------------------------------------------------------------------------
// LayerNorm over last dim D=1024 of (x + res): out = LN(x+res)*g + b.
// res may be null (final LN). In-place safe when out == x (per-row regs).
// ---------------------------------------------------------------------------
__global__ __launch_bounds__(256)
void ln_kernel(const float* __restrict__ x, const float* __restrict__ res,
               const float* __restrict__ g, const float* __restrict__ b,
               float* __restrict__ out)
{
    int row = blockIdx.x;
    const float* xr = x + (long)row * ND;
    const float* rr = res ? res + (long)row * ND : nullptr;
    float* o = out + (long)row * ND;
    int tid = threadIdx.x;
    __shared__ float red[256];

    float v[4];
    float lsum = 0.0f;
    #pragma unroll
    for (int it = 0; it < 4; it++) {
        int j = tid + it * 256;
        float t = xr[j] + (rr ? rr[j] : 0.0f);
        v[it] = t;
        lsum += t;
    }
    red[tid] = lsum; __syncthreads();
    for (int o2 = 128; o2 > 0; o2 >>= 1) {
        if (tid < o2) red[tid] += red[tid + o2];
        __syncthreads();
    }
    float mu = red[0] * (1.0f / ND); __syncthreads();

    float lvar = 0.0f;
    #pragma unroll
    for (int it = 0; it < 4; it++) {
        float d = v[it] - mu;
        lvar += d * d;
    }
    red[tid] = lvar; __syncthreads();
    for (int o2 = 128; o2 > 0; o2 >>= 1) {
        if (tid < o2) red[tid] += red[tid + o2];
        __syncthreads();
    }
    float rstd = rsqrtf(red[0] * (1.0f / ND) + 1e-5f);

    #pragma unroll
    for (int it = 0; it < 4; it++) {
        int j = tid + it * 256;
        o[j] = (v[it] - mu) * rstd * g[j] + b[j];
    }
}

// ---------------------------------------------------------------------------
// Launch
// ---------------------------------------------------------------------------
extern "C" void kernel_launch(void* const* d_in, const int* in_sizes, int n_in,
                              void* d_out, int out_size)
{
    const int*   tokens = (const int*)  d_in[0];
    // d_in[1] = mask (causal; handled analytically)
    const float* emb    = (const float*)d_in[2];
    const float* pe     = (const float*)d_in[3];
    const float* ln1_g  = (const float*)d_in[4];
    const float* ln1_b  = (const float*)d_in[5];
    const float* w1     = (const float*)d_in[6];
    const float* b1     = (const float*)d_in[7];
    const float* w2     = (const float*)d_in[8];
    const float* b2     = (const float*)d_in[9];
    const float* ln2_g  = (const float*)d_in[10];
    const float* ln2_b  = (const float*)d_in[11];
    const float* lnf_g  = (const float*)d_in[12];
    const float* lnf_b  = (const float*)d_in[13];
    const float* headW  = (const float*)d_in[14];
    const float* headb  = (const float*)d_in[15];

    float* out      = (float*)d_out;
    float* logits   = out;                               // [B,S,V]
    float* attn_all = out + (long)NB * NS * NV;          // [L,B,S,S]

    float *x, *tmp, *h;
    cudaGetSymbolAddress((void**)&x,   g_x);
    cudaGetSymbolAddress((void**)&tmp, g_tmp);
    cudaGetSymbolAddress((void**)&h,   g_h);

    const int ROWS = NB * NS;           // 4096
    const float inv_scale = 1.0f / 32.0f;

    embed_kernel<<<ROWS, 256>>>(tokens, emb, pe, x);

    for (int l = 0; l < NL; l++) {
        float* attnL = attn_all + (long)l * NB * NS * NS;

        // scores = x @ x^T / sqrt(D)  (per batch) — skip fully-masked blocks
        sgemm_kernel<true, false, true, false><<<dim3(NS / 128, NS / 128, NB), 256>>>(
            x, x, attnL, NS, NS, ND,
            (long)NS * ND, (long)NS * ND, (long)NS * NS,
            inv_scale, nullptr);

        // causal softmax in place
        softmax_kernel<<<ROWS, 256>>>(attnL);

        // attn_out = attn @ x  (per batch) — K-loop truncated at diagonal
        sgemm_kernel<false, false, false, true><<<dim3(ND / 128, NS / 128, NB), 256>>>(
            attnL, x, tmp, NS, ND, NS,
            (long)NS * NS, (long)NS * ND, (long)NS * ND,
            1.0f, nullptr);

        // x = LN(x + attn_out)
        ln_kernel<<<ROWS, 256>>>(x, tmp, ln1_g + l * ND, ln1_b + l * ND, x);

        // h = relu(x @ w1 + b1)
        sgemm_kernel<false, true, false, false><<<dim3(NF / 128, ROWS / 128, 1), 256>>>(
            x, w1 + (long)l * ND * NF, h, ROWS, NF, ND,
            0, 0, 0, 1.0f, b1 + (long)l * NF);

        // ffn_out = h @ w2 + b2
        sgemm_kernel<false, false, false, false><<<dim3(ND / 128, ROWS / 128, 1), 256>>>(
            h, w2 + (long)l * NF * ND, tmp, ROWS, ND, NF,
            0, 0, 0, 1.0f, b2 + (long)l * ND);

        // x = LN(x + ffn_out)
        ln_kernel<<<ROWS, 256>>>(x, tmp, ln2_g + l * ND, ln2_b + l * ND, x);
    }

    // final LN
    ln_kernel<<<ROWS, 256>>>(x, nullptr, lnf_g, lnf_b, x);

    // logits = x @ headW + headb
    sgemm_kernel<false, false, false, false><<<dim3(NV / 128, ROWS / 128, 1), 256>>>(
        x, headW, logits, ROWS, NV, ND,
        0, 0, 0, 1.0f, headb);
}

// round 4
// speedup vs baseline: 2.7706x; 2.3587x over previous
#include <cuda_runtime.h>
#include <cuda_bf16.h>
#include <cstdint>

// Problem constants
#define NB 4
#define NS 1024
#define ND 1024
#define NF 4096
#define NV 32000
#define NL 4

// ---------------------------------------------------------------------------
// Scratch (device globals: no allocation allowed)
// ---------------------------------------------------------------------------
__device__ float g_x  [(size_t)NB * NS * ND];    // activation stream fp32
__device__ float g_tmp[(size_t)NB * NS * ND];    // attn_out / ffn_out fp32

__device__ __nv_bfloat16 g_xh [(size_t)NB * NS * ND];
__device__ __nv_bfloat16 g_xl [(size_t)NB * NS * ND];
__device__ __nv_bfloat16 g_xth[(size_t)NB * ND * NS];   // x^T per batch
__device__ __nv_bfloat16 g_xtl[(size_t)NB * ND * NS];
__device__ __nv_bfloat16 g_ah [(size_t)NB * NS * NS];   // attn probs split
__device__ __nv_bfloat16 g_al [(size_t)NB * NS * NS];
__device__ __nv_bfloat16 g_hh [(size_t)NB * NS * NF];   // ffn hidden split
__device__ __nv_bfloat16 g_hl [(size_t)NB * NS * NF];
__device__ __nv_bfloat16 g_w1h[(size_t)NL * NF * ND];   // w1^T split
__device__ __nv_bfloat16 g_w1l[(size_t)NL * NF * ND];
__device__ __nv_bfloat16 g_w2h[(size_t)NL * ND * NF];   // w2^T split
__device__ __nv_bfloat16 g_w2l[(size_t)NL * ND * NF];
__device__ __nv_bfloat16 g_wvh[(size_t)NV * ND];        // headW^T split
__device__ __nv_bfloat16 g_wvl[(size_t)NV * ND];

// ---------------------------------------------------------------------------
// Helpers
// ---------------------------------------------------------------------------
__device__ __forceinline__ uint32_t smem_u32(const void* p) {
    return (uint32_t)__cvta_generic_to_shared(p);
}
__device__ __forceinline__ void split_bf16(float v, __nv_bfloat16& h, __nv_bfloat16& l) {
    h = __float2bfloat16(v);
    l = __float2bfloat16(v - __bfloat162float(h));
}

#define CP16(smem, gptr) \
    asm volatile("cp.async.cg.shared.global [%0], [%1], 16;" :: "r"(smem), "l"(gptr))
#define CP_COMMIT() asm volatile("cp.async.commit_group;" ::: "memory")
#define CP_WAIT0() asm volatile("cp.async.wait_group 0;" ::: "memory")
#define CP_WAIT1() asm volatile("cp.async.wait_group 1;" ::: "memory")

#define LDSM_X4(r0, r1, r2, r3, addr) \
    asm volatile("ldmatrix.sync.aligned.m8n8.x4.shared.b16 {%0,%1,%2,%3}, [%4];" \
                 : "=r"(r0), "=r"(r1), "=r"(r2), "=r"(r3) : "r"(addr))

#define MMA16816(c, a, b) \
    asm("mma.sync.aligned.m16n8k16.row.col.f32.bf16.bf16.f32 " \
        "{%0,%1,%2,%3}, {%4,%5,%6,%7}, {%8,%9}, {%0,%1,%2,%3};" \
        : "+f"((c)[0]), "+f"((c)[1]), "+f"((c)[2]), "+f"((c)[3]) \
        : "r"((a)[0]), "r"((a)[1]), "r"((a)[2]), "r"((a)[3]), "r"((b)[0]), "r"((b)[1]))

// ---------------------------------------------------------------------------
// HMMA GEMM: C[M,N] = alpha * (Ah@Bh^T + Ah@Bl^T + Al@Bh^T) (+bias)(+relu).
// A as Ah/Al [M,K] row-major; B as Bh/Bl [N,K] row-major (K-major).
// Tile: BM=128, BN=128, BK=32. 256 threads, warp grid 2x4 (warp tile 64x32).
// Double-buffered cp.async. Smem rows padded to 80B (conflict-free ldmatrix).
// SPLIT: write bf16 hi/lo. CTRI: skip blocks above diagonal. CKLIM: K->brow+128.
// ---------------------------------------------------------------------------
static constexpr int TILE_B  = 128 * 80;          // 10240 bytes per operand tile
static constexpr int STAGE_B = 4 * TILE_B;        // 40960 bytes per stage
static constexpr int SMEM_DYN = 2 * STAGE_B;      // 81920

template<bool RELU, bool SPLIT, bool CTRI, bool CKLIM>
__global__ __launch_bounds__(256)
void hmma_gemm(const __nv_bfloat16* __restrict__ Ah, const __nv_bfloat16* __restrict__ Al,
               const __nv_bfloat16* __restrict__ Bh, const __nv_bfloat16* __restrict__ Bl,
               float* __restrict__ C, __nv_bfloat16* __restrict__ Ch,
               __nv_bfloat16* __restrict__ Cl,
               int M, int N, int K,
               long sA, long sB, long sC,
               float alpha, const float* __restrict__ bias)
{
    const int brow = blockIdx.y * 128;
    const int bcol = blockIdx.x * 128;
    if (CTRI && bcol > brow) return;

    Ah += (long)blockIdx.z * sA;  Al += (long)blockIdx.z * sA;
    Bh += (long)blockIdx.z * sB;  Bl += (long)blockIdx.z * sB;
    if (C)  C  += (long)blockIdx.z * sC;
    if (Ch) { Ch += (long)blockIdx.z * sC; Cl += (long)blockIdx.z * sC; }

    const int tid  = threadIdx.x;
    const int wid  = tid >> 5;
    const int lane = tid & 31;
    const int wm   = wid & 1;          // warp row (0..1) -> 64 rows
    const int wn   = wid >> 1;         // warp col (0..3) -> 32 cols

    const int K_eff = CKLIM ? (brow + 128 < K ? brow + 128 : K) : K;
    const int nk = K_eff >> 5;

    extern __shared__ __align__(16) char dsm[];
    const uint32_t sbase = smem_u32(dsm);
    __shared__ float s_bias[128];
    if (tid < 128) s_bias[tid] = bias ? bias[bcol + tid] : 0.0f;

    float acc[4][4][4] = {};   // [mi][ni][frag]

    // ldmatrix per-lane address components (element offsets within a tile)
    const int a_row = (lane & 15);                 // + wm*64 + mi*16
    const int a_ko  = (lane >> 4) << 3;            // + ks*16
    const int b_row = ((lane >> 4) << 3) + (lane & 7);  // + wn*32 + p*16
    const int b_ko  = ((lane >> 3) & 1) << 3;           // + ks*16

    // loader: 2048 16B chunks per stage, 8 per thread
    auto load_stage = [&](int stage, int kk) {
        const uint32_t sb = sbase + stage * STAGE_B;
        #pragma unroll
        for (int i = 0; i < 8; i++) {
            int chunk = tid + i * 256;
            int tile = chunk >> 9;             // 0:Ah 1:Al 2:Bh 3:Bl
            int w = chunk & 511;
            int r = w >> 2, c = w & 3;
            const __nv_bfloat16* g;
            if (tile == 0)      g = Ah + (long)(brow + r) * K + kk + c * 8;
            else if (tile == 1) g = Al + (long)(brow + r) * K + kk + c * 8;
            else if (tile == 2) g = Bh + (long)(bcol + r) * K + kk + c * 8;
            else                g = Bl + (long)(bcol + r) * K + kk + c * 8;
            CP16(sb + tile * TILE_B + r * 80 + c * 16, g);
        }
    };

    load_stage(0, 0);
    CP_COMMIT();

    for (int kc = 0; kc < nk; kc++) {
        if (kc + 1 < nk) {
            load_stage((kc + 1) & 1, (kc + 1) * 32);
            CP_COMMIT();
            CP_WAIT1();
        } else {
            CP_WAIT0();
        }
        __syncthreads();

        const uint32_t st = sbase + (kc & 1) * STAGE_B;
        const uint32_t ahb = st;
        const uint32_t alb = st + TILE_B;
        const uint32_t bhb = st + 2 * TILE_B;
        const uint32_t blb = st + 3 * TILE_B;

        #pragma unroll
        for (int ks = 0; ks < 2; ks++) {
            const int ak = (ks * 16 + a_ko) * 2;
            const int bk = (ks * 16 + b_ko) * 2;

            uint32_t af[4][4], bf[4][2];
            #pragma unroll
            for (int mi = 0; mi < 4; mi++) {
                uint32_t ad = ahb + (wm * 64 + mi * 16 + a_row) * 80 + ak;
                LDSM_X4(af[mi][0], af[mi][1], af[mi][2], af[mi][3], ad);
            }
            #pragma unroll
            for (int p = 0; p < 2; p++) {
                uint32_t bd = bhb + (wn * 32 + p * 16 + b_row) * 80 + bk;
                LDSM_X4(bf[2*p][0], bf[2*p][1], bf[2*p+1][0], bf[2*p+1][1], bd);
            }
            #pragma unroll
            for (int mi = 0; mi < 4; mi++)
                #pragma unroll
                for (int ni = 0; ni < 4; ni++)
                    MMA16816(acc[mi][ni], af[mi], bf[ni]);   // Ah*Bh

            uint32_t lf[4][2];
            #pragma unroll
            for (int p = 0; p < 2; p++) {
                uint32_t bd = blb + (wn * 32 + p * 16 + b_row) * 80 + bk;
                LDSM_X4(lf[2*p][0], lf[2*p][1], lf[2*p+1][0], lf[2*p+1][1], bd);
            }
            #pragma unroll
            for (int mi = 0; mi < 4; mi++)
                #pragma unroll
                for (int ni = 0; ni < 4; ni++)
                    MMA16816(acc[mi][ni], af[mi], lf[ni]);   // Ah*Bl

            #pragma unroll
            for (int mi = 0; mi < 4; mi++) {
                uint32_t ad = alb + (wm * 64 + mi * 16 + a_row) * 80 + ak;
                LDSM_X4(af[mi][0], af[mi][1], af[mi][2], af[mi][3], ad);
            }
            #pragma unroll
            for (int mi = 0; mi < 4; mi++)
                #pragma unroll
                for (int ni = 0; ni < 4; ni++)
                    MMA16816(acc[mi][ni], af[mi], bf[ni]);   // Al*Bh
        }
        __syncthreads();
    }

    // epilogue
    const int g4 = lane >> 2, t4 = lane & 3;
    #pragma unroll
    for (int mi = 0; mi < 4; mi++) {
        const int r0 = brow + wm * 64 + mi * 16 + g4;
        #pragma unroll
        for (int ni = 0; ni < 4; ni++) {
            const int c0 = bcol + wn * 32 + ni * 8 + t4 * 2;
            const int cl = c0 - bcol;
            float v0 = acc[mi][ni][0] * alpha + s_bias[cl];
            float v1 = acc[mi][ni][1] * alpha + s_bias[cl + 1];
            float v2 = acc[mi][ni][2] * alpha + s_bias[cl];
            float v3 = acc[mi][ni][3] * alpha + s_bias[cl + 1];
            if (RELU) {
                v0 = fmaxf(v0, 0.0f); v1 = fmaxf(v1, 0.0f);
                v2 = fmaxf(v2, 0.0f); v3 = fmaxf(v3, 0.0f);
            }
            if (SPLIT) {
                __nv_bfloat16 h0, l0, h1, l1;
                __nv_bfloat162 hp, lp;
                long b0 = (long)r0 * N + c0;
                split_bf16(v0, h0, l0); split_bf16(v1, h1, l1);
                hp.x = h0; hp.y = h1; lp.x = l0; lp.y = l1;
                *(__nv_bfloat162*)(Ch + b0) = hp;
                *(__nv_bfloat162*)(Cl + b0) = lp;
                long b1 = (long)(r0 + 8) * N + c0;
                split_bf16(v2, h0, l0); split_bf16(v3, h1, l1);
                hp.x = h0; hp.y = h1; lp.x = l0; lp.y = l1;
                *(__nv_bfloat162*)(Ch + b1) = hp;
                *(__nv_bfloat162*)(Cl + b1) = lp;
            } else {
                float2 p0 = { v0, v1 }, p1 = { v2, v3 };
                *(float2*)(C + (long)r0 * N + c0)       = p0;
                *(float2*)(C + (long)(r0 + 8) * N + c0) = p1;
            }
        }
    }
}

// ---------------------------------------------------------------------------
// Transpose + split: out[c][r] = split(in[r][c]); batched via z.
// ---------------------------------------------------------------------------
__global__ void transpose_split_kernel(const float* __restrict__ in,
                                       __nv_bfloat16* __restrict__ oh,
                                       __nv_bfloat16* __restrict__ ol,
                                       int R, int C, long sIn, long sOut)
{
    __shared__ float t[32][33];
    in += (long)blockIdx.z * sIn;
    oh += (long)blockIdx.z * sOut;
    ol += (long)blockIdx.z * sOut;
    int r0 = blockIdx.y * 32, c0 = blockIdx.x * 32;
    int tx = threadIdx.x, ty = threadIdx.y;
    #pragma unroll
    for (int k = 0; k < 32; k += 8)
        t[ty + k][tx] = in[(long)(r0 + ty + k) * C + c0 + tx];
    __syncthreads();
    #pragma unroll
    for (int k = 0; k < 32; k += 8) {
        float v = t[tx][ty + k];
        long o = (long)(c0 + ty + k) * R + r0 + tx;
        __nv_bfloat16 h, l; split_bf16(v, h, l);
        oh[o] = h; ol[o] = l;
    }
}

// ---------------------------------------------------------------------------
// Embedding (+ split)
// ---------------------------------------------------------------------------
__global__ void embed_kernel(const int* __restrict__ tokens,
                             const float* __restrict__ emb,
                             const float* __restrict__ pe,
                             float* __restrict__ x,
                             __nv_bfloat16* __restrict__ xh,
                             __nv_bfloat16* __restrict__ xl)
{
    int row = blockIdx.x;
    int s = row & (NS - 1);
    int tok = tokens[row];
    const float scale = 32.0f;
    const float* e = emb + (long)tok * ND;
    const float* p = pe + (long)s * ND;
    long base = (long)row * ND;
    for (int d = threadIdx.x; d < ND; d += blockDim.x) {
        float v = e[d] * scale + p[d];
        x[base + d] = v;
        __nv_bfloat16 h, l; split_bf16(v, h, l);
        xh[base + d] = h; xl[base + d] = l;
    }
}

// ---------------------------------------------------------------------------
// Causal softmax in place (+ split attn probs)
// ---------------------------------------------------------------------------
__global__ __launch_bounds__(256)
void softmax_kernel(float* __restrict__ attn,
                    __nv_bfloat16* __restrict__ ah, __nv_bfloat16* __restrict__ al)
{
    int row = blockIdx.x;            // b*S + s
    int s = row & (NS - 1);
    long base = (long)row * NS;
    float* p = attn + base;
    int tid = threadIdx.x;
    __shared__ float red[256];

    float vals[4];
    float mx = -1e30f;
    #pragma unroll
    for (int it = 0; it < 4; it++) {
        int j = tid + it * 256;
        float v = (j <= s) ? p[j] : -1e30f;
        vals[it] = v;
        mx = fmaxf(mx, v);
    }
    red[tid] = mx; __syncthreads();
    for (int o = 128; o > 0; o >>= 1) {
        if (tid < o) red[tid] = fmaxf(red[tid], red[tid + o]);
        __syncthreads();
    }
    mx = red[0]; __syncthreads();

    float sum = 0.0f;
    #pragma unroll
    for (int it = 0; it < 4; it++) {
        int j = tid + it * 256;
        float e = (j <= s) ? __expf(vals[it] - mx) : 0.0f;
        vals[it] = e;
        sum += e;
    }
    red[tid] = sum; __syncthreads();
    for (int o = 128; o > 0; o >>= 1) {
        if (tid < o) red[tid] += red[tid + o];
        __syncthreads();
    }
    float inv = 1.0f / red[0];
    #pragma unroll
    for (int it = 0; it < 4; it++) {
        int j = tid + it * 256;
        float v = vals[it] * inv;
        p[j] = v;
        __nv_bfloat16 h, l; split_bf16(v, h, l);
        ah[base + j] = h; al[base + j] = l;
    }
}

// ---------------------------------------------------------------------------
// LayerNorm of (x + res) (+ split). res may be null.
// ---------------------------------------------------------------------------
__global__ __launch_bounds__(256)
void ln_kernel(const float* __restrict__ x, const float* __restrict__ res,
               const float* __restrict__ g, const float* __restrict__ b,
               float* __restrict__ out,
               __nv_bfloat16* __restrict__ oh, __nv_bfloat16* __restrict__ ol)
{
    int row = blockIdx.x;
    long base = (long)row * ND;
    const float* xr = x + base;
    const float* rr = res ? res + base : nullptr;
    int tid = threadIdx.x;
    __shared__ float red[256];

    float v[4];
    float lsum = 0.0f;
    #pragma unroll
    for (int it = 0; it < 4; it++) {
        int j = tid + it * 256;
        float t = xr[j] + (rr ? rr[j] : 0.0f);
        v[it] = t;
        lsum += t;
    }
    red[tid] = lsum; __syncthreads();
    for (int o2 = 128; o2 > 0; o2 >>= 1) {
        if (tid < o2) red[tid] += red[tid + o2];
        __syncthreads();
    }
    float mu = red[0] * (1.0f / ND); __syncthreads();

    float lvar = 0.0f;
    #pragma unroll
    for (int it = 0; it < 4; it++) {
        float d = v[it] - mu;
        lvar += d * d;
    }
    red[tid] = lvar; __syncthreads();
    for (int o2 = 128; o2 > 0; o2 >>= 1) {
        if (tid < o2) red[tid] += red[tid + o2];
        __syncthreads();
    }
    float rstd = rsqrtf(red[0] * (1.0f / ND) + 1e-5f);

    #pragma unroll
    for (int it = 0; it < 4; it++) {
        int j = tid + it * 256;
        float o = (v[it] - mu) * rstd * g[j] + b[j];
        out[base + j] = o;
        __nv_bfloat16 h, l; split_bf16(o, h, l);
        oh[base + j] = h; ol[base + j] = l;
    }
}

// ---------------------------------------------------------------------------
// Launch
// ---------------------------------------------------------------------------
extern "C" void kernel_launch(void* const* d_in, const int* in_sizes, int n_in,
                              void* d_out, int out_size)
{
    const int*   tokens = (const int*)  d_in[0];
    const float* emb    = (const float*)d_in[2];
    const float* pe     = (const float*)d_in[3];
    const float* ln1_g  = (const float*)d_in[4];
    const float* ln1_b  = (const float*)d_in[5];
    const float* w1     = (const float*)d_in[6];
    const float* b1     = (const float*)d_in[7];
    const float* w2     = (const float*)d_in[8];
    const float* b2     = (const float*)d_in[9];
    const float* ln2_g  = (const float*)d_in[10];
    const float* ln2_b  = (const float*)d_in[11];
    const float* lnf_g  = (const float*)d_in[12];
    const float* lnf_b  = (const float*)d_in[13];
    const float* headW  = (const float*)d_in[14];
    const float* headb  = (const float*)d_in[15];

    float* out      = (float*)d_out;
    float* logits   = out;                               // [B,S,V]
    float* attn_all = out + (long)NB * NS * NV;          // [L,B,S,S]

    float *x, *tmp;
    cudaGetSymbolAddress((void**)&x,   g_x);
    cudaGetSymbolAddress((void**)&tmp, g_tmp);
    __nv_bfloat16 *xh, *xl, *xth, *xtl, *ah, *al, *hh, *hl;
    __nv_bfloat16 *w1h, *w1l, *w2h, *w2l, *wvh, *wvl;
    cudaGetSymbolAddress((void**)&xh,  g_xh);  cudaGetSymbolAddress((void**)&xl,  g_xl);
    cudaGetSymbolAddress((void**)&xth, g_xth); cudaGetSymbolAddress((void**)&xtl, g_xtl);
    cudaGetSymbolAddress((void**)&ah,  g_ah);  cudaGetSymbolAddress((void**)&al,  g_al);
    cudaGetSymbolAddress((void**)&hh,  g_hh);  cudaGetSymbolAddress((void**)&hl,  g_hl);
    cudaGetSymbolAddress((void**)&w1h, g_w1h); cudaGetSymbolAddress((void**)&w1l, g_w1l);
    cudaGetSymbolAddress((void**)&w2h, g_w2h); cudaGetSymbolAddress((void**)&w2l, g_w2l);
    cudaGetSymbolAddress((void**)&wvh, g_wvh); cudaGetSymbolAddress((void**)&wvl, g_wvl);

    cudaFuncSetAttribute(hmma_gemm<false, false, true,  false>,
                         cudaFuncAttributeMaxDynamicSharedMemorySize, SMEM_DYN);
    cudaFuncSetAttribute(hmma_gemm<false, false, false, true>,
                         cudaFuncAttributeMaxDynamicSharedMemorySize, SMEM_DYN);
    cudaFuncSetAttribute(hmma_gemm<true,  true,  false, false>,
                         cudaFuncAttributeMaxDynamicSharedMemorySize, SMEM_DYN);
    cudaFuncSetAttribute(hmma_gemm<false, false, false, false>,
                         cudaFuncAttributeMaxDynamicSharedMemorySize, SMEM_DYN);

    const int ROWS = NB * NS;           // 4096
    const dim3 tb(32, 8);

    // weight transposes + splits (deterministic, every launch)
    transpose_split_kernel<<<dim3(NF / 32, ND / 32, NL), tb>>>(
        w1, w1h, w1l, ND, NF, (long)ND * NF, (long)NF * ND);
    transpose_split_kernel<<<dim3(ND / 32, NF / 32, NL), tb>>>(
        w2, w2h, w2l, NF, ND, (long)NF * ND, (long)ND * NF);
    transpose_split_kernel<<<dim3(NV / 32, ND / 32, 1), tb>>>(
        headW, wvh, wvl, ND, NV, 0, 0);

    embed_kernel<<<ROWS, 256>>>(tokens, emb, pe, x, xh, xl);

    for (int l = 0; l < NL; l++) {
        float* attnL = attn_all + (long)l * NB * NS * NS;

        // x^T per batch (B-operand of attn@x)
        transpose_split_kernel<<<dim3(ND / 32, NS / 32, NB), tb>>>(
            x, xth, xtl, NS, ND, (long)NS * ND, (long)ND * NS);

        // scores = x @ x^T / 32 (causal block skip)
        hmma_gemm<false, false, true, false><<<dim3(8, 8, NB), 256, SMEM_DYN>>>(
            xh, xl, xh, xl, attnL, nullptr, nullptr,
            NS, NS, ND, (long)NS * ND, (long)NS * ND, (long)NS * NS,
            1.0f / 32.0f, nullptr);

        softmax_kernel<<<ROWS, 256>>>(attnL, ah, al);

        // attn_out = attn @ x  (K truncated at diagonal)
        hmma_gemm<false, false, false, true><<<dim3(8, 8, NB), 256, SMEM_DYN>>>(
            ah, al, xth, xtl, tmp, nullptr, nullptr,
            NS, ND, NS, (long)NS * NS, (long)ND * NS, (long)NS * ND,
            1.0f, nullptr);

        ln_kernel<<<ROWS, 256>>>(x, tmp, ln1_g + l * ND, ln1_b + l * ND, x, xh, xl);

        // h = relu(x @ w1 + b1)  -> split bf16 only
        hmma_gemm<true, true, false, false><<<dim3(NF / 128, ROWS / 128, 1), 256, SMEM_DYN>>>(
            xh, xl, w1h + (long)l * NF * ND, w1l + (long)l * NF * ND,
            nullptr, hh, hl,
            ROWS, NF, ND, 0, 0, 0, 1.0f, b1 + (long)l * NF);

        // ffn_out = h @ w2 + b2
        hmma_gemm<false, false, false, false><<<dim3(ND / 128, ROWS / 128, 1), 256, SMEM_DYN>>>(
            hh, hl, w2h + (long)l * ND * NF, w2l + (long)l * ND * NF,
            tmp, nullptr, nullptr,
            ROWS, ND, NF, 0, 0, 0, 1.0f, b2 + (long)l * ND);

        ln_kernel<<<ROWS, 256>>>(x, tmp, ln2_g + l * ND, ln2_b + l * ND, x, xh, xl);
    }

    ln_kernel<<<ROWS, 256>>>(x, nullptr, lnf_g, lnf_b, x, xh, xl);

    // logits = x @ headW + headb
    hmma_gemm<false, false, false, false><<<dim3(NV / 128, ROWS / 128, 1), 256, SMEM_DYN>>>(
        xh, xl, wvh, wvl, logits, nullptr, nullptr,
        ROWS, NV, ND, 0, 0, 0, 1.0f, headb);
}